// round 13
// baseline (speedup 1.0000x reference)
#include <cuda_runtime.h>
#include <cstdint>
#include <math_constants.h>

// Problem constants (fixed by setup_inputs)
#define B_ 4
#define C_ 3
#define M_ 4096
#define N_ 8192
#define K_ 16
#define NEIGH_TOTAL (B_ * C_ * M_ * K_)   // 786432
#define NQ (B_ * M_)                       // 16384 queries
#define NWARP (NQ / 2)                     // 8192 persistent warps

// Scan layout: chunk-blocked SoA. Per batch, per 128-point chunk:
//   X[128] | Y[128] | Z[128] | W[128]   (chunk stride = 512 floats)
__device__ float g_PS[B_ * N_ * 4];
// AoS copy (x,y,z,w) used only for the final neighbor gather.
__device__ float4 g_P4[B_ * N_];

// ---------------------------------------------------------------------------
// f32x2 helpers (Blackwell FFMA2 path — only reachable via PTX)
// ---------------------------------------------------------------------------
__device__ __forceinline__ uint64_t pack2(float a, float b) {
    uint64_t r; asm("mov.b64 %0, {%1,%2};" : "=l"(r) : "f"(a), "f"(b)); return r;
}
__device__ __forceinline__ void unpack2(uint64_t v, float& a, float& b) {
    asm("mov.b64 {%0,%1}, %2;" : "=f"(a), "=f"(b) : "l"(v));
}
__device__ __forceinline__ uint64_t fma2(uint64_t a, uint64_t b, uint64_t c) {
    uint64_t r; asm("fma.rn.f32x2 %0, %1, %2, %3;" : "=l"(r) : "l"(a), "l"(b), "l"(c)); return r;
}
__device__ __forceinline__ uint64_t mul2(uint64_t a, uint64_t b) {
    uint64_t r; asm("mul.rn.f32x2 %0, %1, %2;" : "=l"(r) : "l"(a), "l"(b)); return r;
}
__device__ __forceinline__ uint64_t add2(uint64_t a, uint64_t b) {
    uint64_t r; asm("add.rn.f32x2 %0, %1, %2;" : "=l"(r) : "l"(a), "l"(b)); return r;
}
// 16B load straight into two 64-bit register pairs (LDG.E.128, no repack)
__device__ __forceinline__ void ldg128_2x64(const float* p, uint64_t& a, uint64_t& b) {
    asm("ld.global.nc.v2.u64 {%0,%1}, [%2];" : "=l"(a), "=l"(b) : "l"(p));
}

// ---------------------------------------------------------------------------
// Prep: transpose points (B,C,N) -> blocked SoA + AoS, |p|^2 with the same
// rounding as jnp.sum(p*p): mul, mul, mul, add, add (no FMA fusion).
// ---------------------------------------------------------------------------
__global__ void knn_prep_kernel(const float* __restrict__ points) {
    int t = blockIdx.x * blockDim.x + threadIdx.x;
    if (t >= B_ * N_) return;
    int b = t / N_;
    int n = t - b * N_;
    float x = points[(b * 3 + 0) * N_ + n];
    float y = points[(b * 3 + 1) * N_ + n];
    float z = points[(b * 3 + 2) * N_ + n];
    float w = __fadd_rn(__fadd_rn(__fmul_rn(x, x), __fmul_rn(y, y)), __fmul_rn(z, z));
    g_P4[t] = make_float4(x, y, z, w);
    int c = n >> 7, pos = n & 127;
    float* base = g_PS + (size_t)b * (N_ * 4) + c * 512;
    base[pos]       = x;
    base[128 + pos] = y;
    base[256 + pos] = z;
    base[384 + pos] = w;
}

// ---------------------------------------------------------------------------
// One insert slice: serial distributed insert into the sorted 16-list in
// lanes 0..15. Lexicographic (dist, idx); threshold = rank-15 element.
// Candidate index for src lane: ci = cbasej + 4*src.
// ---------------------------------------------------------------------------
__device__ __forceinline__ void process_slice(
    float d, int cbasej, int lane,
    float& ld, int& li, float& td, int& ti)
{
    const unsigned FULL = 0xFFFFFFFFu;
    unsigned bal = __ballot_sync(FULL, d <= td);
    if (!bal) return;
    do {
        const int src = __ffs(bal) - 1;
        bal &= bal - 1;
        const float cd = __shfl_sync(FULL, d, src);
        const int   ci = cbasej + (src << 2);

        if (cd > td || (cd == td && ci > ti)) continue;

        bool lt = (ld < cd) || (ld == cd && li < ci);
        unsigned mlt = __ballot_sync(FULL, lt) & 0xFFFFu;
        int pos = __popc(mlt);
        float pld = __shfl_up_sync(FULL, ld, 1);
        int   pli = __shfl_up_sync(FULL, li, 1);
        if (pos < 16) {
            if (lane == pos)     { ld = cd;  li = ci;  }
            else if (lane > pos) { ld = pld; li = pli; }
        }
    } while (bal);
    td = __shfl_sync(FULL, ld, 15);
    ti = __shfl_sync(FULL, li, 15);
}

// ---------------------------------------------------------------------------
// Main KNN kernel: persistent warps, 2 queries per warp (queries t and
// t + NWARP), single wave, no tail. Lane l handles points i*128+4l..4l+3.
// Packed f32x2 distance math; per-chunk min filter; bitonic init; serial
// distributed insert. Rounding identical to prior passing kernels:
//   dot = fma(qz,pz, fma(qy,py, mul(qx,px))); d = fma(-2, dot, add(q2,w))
// ---------------------------------------------------------------------------
__global__ __launch_bounds__(256) void knn_kernel(
    const float* __restrict__ query,
    float* __restrict__ out)
{
    const unsigned FULL = 0xFFFFFFFFu;
    const int w    = blockIdx.x * 8 + (threadIdx.x >> 5);   // 0..NWARP-1
    const int lane = threadIdx.x & 31;

    for (int half = 0; half < 2; ++half) {
        const int t = w + half * NWARP;      // query id 0..NQ-1
        const int b = t >> 12;               // batch
        const int m = t & (M_ - 1);          // query row

        const float qx = query[(b * 3 + 0) * M_ + m];
        const float qy = query[(b * 3 + 1) * M_ + m];
        const float qz = query[(b * 3 + 2) * M_ + m];
        const float q2 = __fadd_rn(__fadd_rn(__fmul_rn(qx, qx), __fmul_rn(qy, qy)),
                                   __fmul_rn(qz, qz));

        const uint64_t qxx = pack2(qx, qx);
        const uint64_t qyy = pack2(qy, qy);
        const uint64_t qzz = pack2(qz, qz);
        const uint64_t q22 = pack2(q2, q2);
        const uint64_t m22 = pack2(-2.0f, -2.0f);

        const float* __restrict__ PS = g_PS + (size_t)b * (N_ * 4);

        float ld, td;
        int   li, ti;

        // Distances for the lane's 4 points of chunk at `base`.
#define DIST4(base, d0, d1, d2, d3) {                                       \
            uint64_t x01, x23, y01, y23, z01, z23, w01, w23;                \
            ldg128_2x64((base) +   0 + 4 * lane, x01, x23);                 \
            ldg128_2x64((base) + 128 + 4 * lane, y01, y23);                 \
            ldg128_2x64((base) + 256 + 4 * lane, z01, z23);                 \
            ldg128_2x64((base) + 384 + 4 * lane, w01, w23);                 \
            uint64_t dot01 = fma2(qzz, z01, fma2(qyy, y01, mul2(qxx, x01)));\
            uint64_t dot23 = fma2(qzz, z23, fma2(qyy, y23, mul2(qxx, x23)));\
            uint64_t dd01  = fma2(m22, dot01, add2(q22, w01));              \
            uint64_t dd23  = fma2(m22, dot23, add2(q22, w23));              \
            unpack2(dd01, d0, d1);                                          \
            unpack2(dd23, d2, d3);                                          \
        }

        // ---------------- chunk 0: bitonic init + 3 insert slices ------------
        {
            float d0, d1, d2, d3;
            DIST4(PS, d0, d1, d2, d3);

            // Bitonic sort of (d0, 4*lane) across the warp, ascending lex.
            float sd = d0;
            int   si = 4 * lane;
#pragma unroll
            for (int k = 2; k <= 32; k <<= 1) {
#pragma unroll
                for (int jj = k >> 1; jj > 0; jj >>= 1) {
                    float od = __shfl_xor_sync(FULL, sd, jj);
                    int   oi = __shfl_xor_sync(FULL, si, jj);
                    bool wantMin = ((lane & jj) == 0) == ((lane & k) == 0);
                    bool oless = (od < sd) || (od == sd && oi < si);
                    if (oless == wantMin) { sd = od; si = oi; }
                }
            }
            ld = sd; li = si;                      // lanes 0..15 = ranks 0..15
            td = __shfl_sync(FULL, ld, 15);
            ti = __shfl_sync(FULL, li, 15);

            process_slice(d1, 1, lane, ld, li, td, ti);
            process_slice(d2, 2, lane, ld, li, td, ti);
            process_slice(d3, 3, lane, ld, li, td, ti);
        }

        // ---------------- chunks 1..63: min-filtered fast path ---------------
        for (int i = 1; i < N_ / 128; ++i) {
            const float* base = PS + i * 512;
            float d0, d1, d2, d3;
            DIST4(base, d0, d1, d2, d3);

            // min d <= td  <=>  exists j with d_j <= td (no NaNs) — exact
            const float mm = fminf(fminf(d0, d1), fminf(d2, d3));
            unsigned bal = __ballot_sync(FULL, mm <= td);
            if (!bal) continue;

            const int cb = i * 128;
            process_slice(d0, cb,     lane, ld, li, td, ti);
            process_slice(d1, cb + 1, lane, ld, li, td, ti);
            process_slice(d2, cb + 2, lane, ld, li, td, ti);
            process_slice(d3, cb + 3, lane, ld, li, td, ti);
        }
#undef DIST4

        // ---------------- emit ------------------------------------------------
        if (lane < K_) {
            const int idx = li;
            const float4 p = g_P4[b * N_ + idx];
            // neighbor_points: (B, C, M, K) float32
            out[((b * 3 + 0) * M_ + m) * K_ + lane] = p.x;
            out[((b * 3 + 1) * M_ + m) * K_ + lane] = p.y;
            out[((b * 3 + 2) * M_ + m) * K_ + lane] = p.z;
            // index_batch: (B, M, K), cast to float32 (exact for idx < 2^24)
            out[NEIGH_TOTAL + (b * M_ + m) * K_ + lane] = (float)idx;
        }
    }
}

// ---------------------------------------------------------------------------
// Launcher
// ---------------------------------------------------------------------------
extern "C" void kernel_launch(void* const* d_in, const int* in_sizes, int n_in,
                              void* d_out, int out_size) {
    const float* query  = nullptr;
    const float* points = nullptr;
    for (int i = 0; i < n_in; ++i) {
        if (in_sizes[i] == B_ * C_ * M_)      query  = (const float*)d_in[i];
        else if (in_sizes[i] == B_ * C_ * N_) points = (const float*)d_in[i];
    }
    (void)out_size;

    knn_prep_kernel<<<(B_ * N_ + 255) / 256, 256>>>(points);
    knn_kernel<<<NWARP / 8, 256>>>(query, (float*)d_out);
}

// round 15
// speedup vs baseline: 1.1492x; 1.1492x over previous
#include <cuda_runtime.h>
#include <cstdint>
#include <math_constants.h>

// Problem constants (fixed by setup_inputs)
#define B_ 4
#define C_ 3
#define M_ 4096
#define N_ 8192
#define K_ 16
#define NEIGH_TOTAL (B_ * C_ * M_ * K_)   // 786432

// Scan layout: chunk-blocked SoA. Per batch, per 128-point chunk:
//   X[128] | Y[128] | Z[128] | W[128]   (chunk stride = 512 floats)
__device__ float g_PS[B_ * N_ * 4];
// AoS copy (x,y,z,w) used only for the final neighbor gather.
__device__ float4 g_P4[B_ * N_];

// ---------------------------------------------------------------------------
// f32x2 helpers (Blackwell FFMA2 path — only reachable via PTX)
// ---------------------------------------------------------------------------
__device__ __forceinline__ uint64_t pack2(float a, float b) {
    uint64_t r; asm("mov.b64 %0, {%1,%2};" : "=l"(r) : "f"(a), "f"(b)); return r;
}
__device__ __forceinline__ void unpack2(uint64_t v, float& a, float& b) {
    asm("mov.b64 {%0,%1}, %2;" : "=f"(a), "=f"(b) : "l"(v));
}
__device__ __forceinline__ uint64_t fma2(uint64_t a, uint64_t b, uint64_t c) {
    uint64_t r; asm("fma.rn.f32x2 %0, %1, %2, %3;" : "=l"(r) : "l"(a), "l"(b), "l"(c)); return r;
}
__device__ __forceinline__ uint64_t mul2(uint64_t a, uint64_t b) {
    uint64_t r; asm("mul.rn.f32x2 %0, %1, %2;" : "=l"(r) : "l"(a), "l"(b)); return r;
}
__device__ __forceinline__ uint64_t add2(uint64_t a, uint64_t b) {
    uint64_t r; asm("add.rn.f32x2 %0, %1, %2;" : "=l"(r) : "l"(a), "l"(b)); return r;
}
// 16B load straight into two 64-bit register pairs (LDG.E.128, no repack)
__device__ __forceinline__ void ldg128_2x64(const float* p, uint64_t& a, uint64_t& b) {
    asm("ld.global.nc.v2.u64 {%0,%1}, [%2];" : "=l"(a), "=l"(b) : "l"(p));
}

// ---------------------------------------------------------------------------
// Prep: transpose points (B,C,N) -> blocked SoA + AoS, |p|^2 with the same
// rounding as jnp.sum(p*p): mul, mul, mul, add, add (no FMA fusion).
// ---------------------------------------------------------------------------
__global__ void knn_prep_kernel(const float* __restrict__ points) {
    int t = blockIdx.x * blockDim.x + threadIdx.x;
    if (t >= B_ * N_) return;
    int b = t / N_;
    int n = t - b * N_;
    float x = points[(b * 3 + 0) * N_ + n];
    float y = points[(b * 3 + 1) * N_ + n];
    float z = points[(b * 3 + 2) * N_ + n];
    float w = __fadd_rn(__fadd_rn(__fmul_rn(x, x), __fmul_rn(y, y)), __fmul_rn(z, z));
    g_P4[t] = make_float4(x, y, z, w);
    int c = n >> 7, pos = n & 127;
    float* base = g_PS + (size_t)b * (N_ * 4) + c * 512;
    base[pos]       = x;
    base[128 + pos] = y;
    base[256 + pos] = z;
    base[384 + pos] = w;
}

// ---------------------------------------------------------------------------
// One insert slice: serial distributed insert into the sorted 16-list in
// lanes 0..15. Lexicographic (dist, idx); threshold = rank-15 element.
// Candidate index for src lane: ci = cbasej + 4*src.
// ---------------------------------------------------------------------------
__device__ __forceinline__ void process_slice(
    float d, int cbasej, int lane,
    float& ld, int& li, float& td, int& ti)
{
    const unsigned FULL = 0xFFFFFFFFu;
    unsigned bal = __ballot_sync(FULL, d <= td);
    if (!bal) return;
    do {
        const int src = __ffs(bal) - 1;
        bal &= bal - 1;
        const float cd = __shfl_sync(FULL, d, src);
        const int   ci = cbasej + (src << 2);

        if (cd > td || (cd == td && ci > ti)) continue;

        bool lt = (ld < cd) || (ld == cd && li < ci);
        unsigned mlt = __ballot_sync(FULL, lt) & 0xFFFFu;
        int pos = __popc(mlt);
        float pld = __shfl_up_sync(FULL, ld, 1);
        int   pli = __shfl_up_sync(FULL, li, 1);
        if (pos < 16) {
            if (lane == pos)     { ld = cd;  li = ci;  }
            else if (lane > pos) { ld = pld; li = pli; }
        }
    } while (bal);
    td = __shfl_sync(FULL, ld, 15);
    ti = __shfl_sync(FULL, li, 15);
}

// ---------------------------------------------------------------------------
// Main KNN kernel: one warp per query (round-9 shape: grid 4096 x 128thr).
// Fast path processes 256 points (two independent 128-pt chunks) per
// iteration with ONE combined ballot — double ILP, half the ballots.
// Packed f32x2 distance math; bitonic init; serial distributed insert.
// Rounding identical to prior passing kernels:
//   dot = fma(qz,pz, fma(qy,py, mul(qx,px))); d = fma(-2, dot, add(q2,w))
// ---------------------------------------------------------------------------
__global__ __launch_bounds__(128) void knn_kernel(
    const float* __restrict__ query,
    float* __restrict__ out)
{
    const unsigned FULL = 0xFFFFFFFFu;
    const int warp = threadIdx.x >> 5;
    const int lane = threadIdx.x & 31;
    const int m = blockIdx.x * 4 + warp;   // query row
    const int b = blockIdx.y;              // batch

    const float qx = query[(b * 3 + 0) * M_ + m];
    const float qy = query[(b * 3 + 1) * M_ + m];
    const float qz = query[(b * 3 + 2) * M_ + m];
    const float q2 = __fadd_rn(__fadd_rn(__fmul_rn(qx, qx), __fmul_rn(qy, qy)),
                               __fmul_rn(qz, qz));

    const uint64_t qxx = pack2(qx, qx);
    const uint64_t qyy = pack2(qy, qy);
    const uint64_t qzz = pack2(qz, qz);
    const uint64_t q22 = pack2(q2, q2);
    const uint64_t m22 = pack2(-2.0f, -2.0f);

    const float* __restrict__ PS = g_PS + (size_t)b * (N_ * 4);

    float ld, td;
    int   li, ti;

    // Distances for the lane's 4 points of the 128-pt chunk at `base`.
#define DIST4(base, d0, d1, d2, d3) {                                       \
        uint64_t x01, x23, y01, y23, z01, z23, w01, w23;                    \
        ldg128_2x64((base) +   0 + 4 * lane, x01, x23);                     \
        ldg128_2x64((base) + 128 + 4 * lane, y01, y23);                     \
        ldg128_2x64((base) + 256 + 4 * lane, z01, z23);                     \
        ldg128_2x64((base) + 384 + 4 * lane, w01, w23);                     \
        uint64_t dot01 = fma2(qzz, z01, fma2(qyy, y01, mul2(qxx, x01)));    \
        uint64_t dot23 = fma2(qzz, z23, fma2(qyy, y23, mul2(qxx, x23)));    \
        uint64_t dd01  = fma2(m22, dot01, add2(q22, w01));                  \
        uint64_t dd23  = fma2(m22, dot23, add2(q22, w23));                  \
        unpack2(dd01, d0, d1);                                              \
        unpack2(dd23, d2, d3);                                              \
    }

    // ---------------- chunk 0: bitonic init + 3 insert slices ----------------
    {
        float d0, d1, d2, d3;
        DIST4(PS, d0, d1, d2, d3);

        // Bitonic sort of (d0, 4*lane) across the warp, ascending lex (d,idx).
        float sd = d0;
        int   si = 4 * lane;
#pragma unroll
        for (int k = 2; k <= 32; k <<= 1) {
#pragma unroll
            for (int jj = k >> 1; jj > 0; jj >>= 1) {
                float od = __shfl_xor_sync(FULL, sd, jj);
                int   oi = __shfl_xor_sync(FULL, si, jj);
                bool wantMin = ((lane & jj) == 0) == ((lane & k) == 0);
                bool oless = (od < sd) || (od == sd && oi < si);
                if (oless == wantMin) { sd = od; si = oi; }
            }
        }
        ld = sd; li = si;                       // lanes 0..15 = ranks 0..15
        td = __shfl_sync(FULL, ld, 15);
        ti = __shfl_sync(FULL, li, 15);

        process_slice(d1, 1, lane, ld, li, td, ti);
        process_slice(d2, 2, lane, ld, li, td, ti);
        process_slice(d3, 3, lane, ld, li, td, ti);
    }

    // ---------------- chunk 1: normal filtered chunk --------------------------
    {
        float d0, d1, d2, d3;
        DIST4(PS + 512, d0, d1, d2, d3);
        const float mm = fminf(fminf(d0, d1), fminf(d2, d3));
        unsigned bal = __ballot_sync(FULL, mm <= td);
        if (bal) {
            process_slice(d0, 128, lane, ld, li, td, ti);
            process_slice(d1, 129, lane, ld, li, td, ti);
            process_slice(d2, 130, lane, ld, li, td, ti);
            process_slice(d3, 131, lane, ld, li, td, ti);
        }
    }

    // ------------- chunk pairs 1..31 (points 256..8191): one ballot/256 ------
    for (int i = 1; i < N_ / 256; ++i) {
        const float* base = PS + i * 1024;
        float d0, d1, d2, d3, e0, e1, e2, e3;
        DIST4(base,       d0, d1, d2, d3);      // chunk 2i
        DIST4(base + 512, e0, e1, e2, e3);      // chunk 2i+1 (independent chain)

        const float md = fminf(fminf(d0, d1), fminf(d2, d3));
        const float me = fminf(fminf(e0, e1), fminf(e2, e3));
        const float mm = fminf(md, me);
        // min of 8 <= td  <=>  exists d <= td (no NaNs) — exact filter
        unsigned bal = __ballot_sync(FULL, mm <= td);
        if (!bal) continue;

        const int cb = i * 256;
        process_slice(d0, cb,       lane, ld, li, td, ti);
        process_slice(d1, cb + 1,   lane, ld, li, td, ti);
        process_slice(d2, cb + 2,   lane, ld, li, td, ti);
        process_slice(d3, cb + 3,   lane, ld, li, td, ti);
        process_slice(e0, cb + 128, lane, ld, li, td, ti);
        process_slice(e1, cb + 129, lane, ld, li, td, ti);
        process_slice(e2, cb + 130, lane, ld, li, td, ti);
        process_slice(e3, cb + 131, lane, ld, li, td, ti);
    }
#undef DIST4

    // ---------------- emit ----------------------------------------------------
    if (lane < K_) {
        const int idx = li;
        const float4 p = g_P4[b * N_ + idx];
        // neighbor_points: (B, C, M, K) float32
        out[((b * 3 + 0) * M_ + m) * K_ + lane] = p.x;
        out[((b * 3 + 1) * M_ + m) * K_ + lane] = p.y;
        out[((b * 3 + 2) * M_ + m) * K_ + lane] = p.z;
        // index_batch: (B, M, K), cast to float32 (exact for idx < 2^24)
        out[NEIGH_TOTAL + (b * M_ + m) * K_ + lane] = (float)idx;
    }
}

// ---------------------------------------------------------------------------
// Launcher
// ---------------------------------------------------------------------------
extern "C" void kernel_launch(void* const* d_in, const int* in_sizes, int n_in,
                              void* d_out, int out_size) {
    const float* query  = nullptr;
    const float* points = nullptr;
    for (int i = 0; i < n_in; ++i) {
        if (in_sizes[i] == B_ * C_ * M_)      query  = (const float*)d_in[i];
        else if (in_sizes[i] == B_ * C_ * N_) points = (const float*)d_in[i];
    }
    (void)out_size;

    knn_prep_kernel<<<(B_ * N_ + 255) / 256, 256>>>(points);
    dim3 grid(M_ / 4, B_);
    knn_kernel<<<grid, 128>>>(query, (float*)d_out);
}